// round 13
// baseline (speedup 1.0000x reference)
#include <cuda_runtime.h>
#include <cuda_fp16.h>

#define BSZ 2
#define TLEN 2048
#define NH 16
#define PP 64
#define NN 64
#define CHL 64                 // chunk length
#define NCH (TLEN / CHL)       // 32 chunks
#define LDS_ (NN + 4)          // padded row stride (68) for sB/sC
#define IDX(r,c)  ((r) * LDS_ + (c))
#define IDXX(r,c) ((r) * NN + (c))    // unpadded (sX: all accesses row-constant)

// Scratch (device globals; allocation-free). State scratch in fp16 (half traffic).
__device__ __half2 g_S [BSZ * NH * NCH * PP * NN / 2];  // per-chunk local state
__device__ __half2 g_H0[BSZ * NH * NCH * PP * NN / 2];  // state entering chunk
__device__ float   g_A [BSZ * NH * NCH];                // per-chunk total decay
__device__ float   g_a [BSZ * NH * NCH * CHL];          // a_t = exp(negA*cum_t)

__device__ __forceinline__ void cp16(void* smem_dst, const void* gsrc) {
    unsigned d = (unsigned)__cvta_generic_to_shared(smem_dst);
    asm volatile("cp.async.cg.shared.global [%0], [%1], 16;" :: "r"(d), "l"(gsrc));
}
__device__ __forceinline__ void cp_commit_wait() {
    asm volatile("cp.async.commit_group;");
    asm volatile("cp.async.wait_group 0;");
}

// ---------------------------------------------------------------------------
// KA: fused intra-chunk kernel. One block per (b,h,c), 256 threads.
//   GEMM1 : G[t,s]  = sum_n C[t,n] B[s,n]
//   W^T   : sW[s,t] = (s<=t) ? exp(negA*(cum_t-cum_s))*delta_s*G : 0  (aliases sC)
//   GEMM-S: S[p,n]  = sum_s r_s B[s,n] X[s,p]   -> g_S (fp16); chunk 31 also -> hlast fp32
//   GEMM2 : y[t,p]  = sum_{s<=t} W[t,s] X[s,p]
// ---------------------------------------------------------------------------
__global__ __launch_bounds__(256) void kA_intra(
    const float* __restrict__ X,      // [B,T,H,P]
    const float* __restrict__ delta,  // [B,T,H]
    const float* __restrict__ Bm,     // [B,T,N]
    const float* __restrict__ Cm,     // [B,T,N]
    const float* __restrict__ A_log,  // [H]
    float* __restrict__ y,            // [B,T,H,P]
    float* __restrict__ hlast)        // [B,H,P,N]
{
    extern __shared__ float smem[];
    float* sB = smem;                 // [CHL][LDS_]
    float* sC = sB + CHL * LDS_;      // [CHL][LDS_], later W^T
    float* sX = sC + CHL * LDS_;      // [CHL][NN] unpadded
    float* sW = sC;

    __shared__ float sh_d[CHL], sh_cum[CHL], sh_r[CHL];
    __shared__ float sh_wsum[2];

    const int blk = blockIdx.x;            // (b*NH+h)*NCH + c
    const int c  = blk % NCH;
    const int hh = (blk / NCH) % NH;
    const int b  = blk / (NCH * NH);
    const int t0 = c * CHL;
    const int tid = threadIdx.x;
    const int lane = tid & 31;

    const float negA = -__expf(A_log[hh]);

    // ---- stage B, C, X via cp.async ----
    for (int i = tid; i < CHL * NN / 4; i += 256) {
        const int r = i >> 4, q = i & 15;
        cp16(&sB[IDX(r, q * 4)],  (const float4*)(Bm + ((size_t)b * TLEN + t0 + r) * NN) + q);
        cp16(&sC[IDX(r, q * 4)],  (const float4*)(Cm + ((size_t)b * TLEN + t0 + r) * NN) + q);
        cp16(&sX[IDXX(r, q * 4)], (const float4*)(X + (((size_t)b * TLEN + t0 + r) * NH + hh) * PP) + q);
    }

    // ---- delta + warp-level inclusive scan (phase 1) ----
    if (tid < CHL) {
        const float d = __ldg(delta + ((size_t)b * TLEN + t0 + tid) * NH + hh);
        sh_d[tid] = d;
        float v = d;
        #pragma unroll
        for (int off = 1; off < 32; off <<= 1) {
            const float t = __shfl_up_sync(0xffffffffu, v, off);
            if (lane >= off) v += t;
        }
        sh_cum[tid] = v;
        if (lane == 31) sh_wsum[tid >> 5] = v;
    }
    cp_commit_wait();
    __syncthreads();   // sync1: staging + scan phase1 done

    // ---- scan phase 2: cross-warp fixup, r_s, a_t, A_c ----
    if (tid < CHL) {
        const float cum = sh_cum[tid] + (tid >= 32 ? sh_wsum[0] : 0.f);
        sh_cum[tid] = cum;
        const float cumTot = sh_wsum[0] + sh_wsum[1];
        g_a[(size_t)blk * CHL + tid] = __expf(negA * cum);
        sh_r[tid] = __expf(negA * (cumTot - cum)) * sh_d[tid];
        if (tid == 0) g_A[blk] = __expf(negA * cumTot);
    }

    const int i = tid & 15;
    const int j = tid >> 4;

    // ---- GEMM1: G[t,s], t = j+16tj, s = i+16si, reduce over n ----
    float g[4][4];
    #pragma unroll
    for (int a0 = 0; a0 < 4; ++a0)
        #pragma unroll
        for (int a1 = 0; a1 < 4; ++a1) g[a0][a1] = 0.f;

    #pragma unroll 4
    for (int n4 = 0; n4 < NN / 4; ++n4) {
        float4 cv[4], bv[4];
        #pragma unroll
        for (int tj = 0; tj < 4; ++tj) cv[tj] = *(const float4*)&sC[IDX(j + 16 * tj, n4 * 4)];
        #pragma unroll
        for (int si = 0; si < 4; ++si) bv[si] = *(const float4*)&sB[IDX(i + 16 * si, n4 * 4)];
        #pragma unroll
        for (int tj = 0; tj < 4; ++tj)
            #pragma unroll
            for (int si = 0; si < 4; ++si) {
                g[tj][si] = fmaf(cv[tj].x, bv[si].x, g[tj][si]);
                g[tj][si] = fmaf(cv[tj].y, bv[si].y, g[tj][si]);
                g[tj][si] = fmaf(cv[tj].z, bv[si].z, g[tj][si]);
                g[tj][si] = fmaf(cv[tj].w, bv[si].w, g[tj][si]);
            }
    }
    __syncthreads();   // sync2: GEMM1 reads of sB/sC done; sh_cum finalized

    // ---- write W transposed into sC's space ----
    #pragma unroll
    for (int tj = 0; tj < 4; ++tj) {
        const int t = j + 16 * tj;
        const float ct = sh_cum[t];
        #pragma unroll
        for (int si = 0; si < 4; ++si) {
            const int s = i + 16 * si;
            const float arg = negA * (ct - sh_cum[s]);
            const float e = __expf(fminf(arg, 0.f));
            sW[IDX(s, t)] = (s <= t) ? e * sh_d[s] * g[tj][si] : 0.f;
        }
    }
    // ---- scale sB in place by r_s ----
    for (int idx = tid; idx < CHL * NN / 4; idx += 256) {
        const int r = idx >> 4, q = idx & 15;
        float4 v = *(float4*)&sB[IDX(r, q * 4)];
        const float rr = sh_r[r];
        v.x *= rr; v.y *= rr; v.z *= rr; v.w *= rr;
        *(float4*)&sB[IDX(r, q * 4)] = v;
    }
    __syncthreads();   // sync3: sW and scaled sB visible

    // ---- GEMM-S: S[p][n] = sum_s sB'[s,n] sX[s,p]; n=4i.., p=4j.. ----
    {
        float acc[4][4];   // [pj][ni]
        #pragma unroll
        for (int a0 = 0; a0 < 4; ++a0)
            #pragma unroll
            for (int a1 = 0; a1 < 4; ++a1) acc[a0][a1] = 0.f;

        #pragma unroll 8
        for (int s = 0; s < CHL; ++s) {
            const float4 bv = *(const float4*)&sB[IDX(s, 4 * i)];
            const float4 xv = *(const float4*)&sX[IDXX(s, 4 * j)];
            acc[0][0] = fmaf(xv.x, bv.x, acc[0][0]);
            acc[0][1] = fmaf(xv.x, bv.y, acc[0][1]);
            acc[0][2] = fmaf(xv.x, bv.z, acc[0][2]);
            acc[0][3] = fmaf(xv.x, bv.w, acc[0][3]);
            acc[1][0] = fmaf(xv.y, bv.x, acc[1][0]);
            acc[1][1] = fmaf(xv.y, bv.y, acc[1][1]);
            acc[1][2] = fmaf(xv.y, bv.z, acc[1][2]);
            acc[1][3] = fmaf(xv.y, bv.w, acc[1][3]);
            acc[2][0] = fmaf(xv.z, bv.x, acc[2][0]);
            acc[2][1] = fmaf(xv.z, bv.y, acc[2][1]);
            acc[2][2] = fmaf(xv.z, bv.z, acc[2][2]);
            acc[2][3] = fmaf(xv.z, bv.w, acc[2][3]);
            acc[3][0] = fmaf(xv.w, bv.x, acc[3][0]);
            acc[3][1] = fmaf(xv.w, bv.y, acc[3][1]);
            acc[3][2] = fmaf(xv.w, bv.z, acc[3][2]);
            acc[3][3] = fmaf(xv.w, bv.w, acc[3][3]);
        }
        // fp16 store of S (coalesced: lane i -> 8*i bytes)
        __half2* Sp = g_S + (size_t)blk * (PP * NN / 2);
        #pragma unroll
        for (int pj = 0; pj < 4; ++pj) {
            const int p = 4 * j + pj;
            __half2 h01 = __floats2half2_rn(acc[pj][0], acc[pj][1]);
            __half2 h23 = __floats2half2_rn(acc[pj][2], acc[pj][3]);
            uint2 u;
            u.x = *(unsigned*)&h01;
            u.y = *(unsigned*)&h23;
            *(uint2*)(Sp + p * (NN / 2) + 2 * i) = u;
        }
        // chunk 31: exact fp32 S -> hlast (K2 adds the ~e-14 correction)
        if (c == NCH - 1) {
            float* hp = hlast + ((size_t)(b * NH + hh)) * PP * NN;
            #pragma unroll
            for (int pj = 0; pj < 4; ++pj) {
                const int p = 4 * j + pj;
                *(float4*)(hp + p * NN + 4 * i) =
                    make_float4(acc[pj][0], acc[pj][1], acc[pj][2], acc[pj][3]);
            }
        }
    }

    // ---- GEMM2: Y1[t,p] = sum_{s<=t} W[t,s] X[s,p]; t=4j.., p=4i.. ----
    {
        const int sBound = ((tid >> 5) + 1) * 8;   // warp-uniform triangular bound
        float acc[4][4];   // [tj][pi]
        #pragma unroll
        for (int a0 = 0; a0 < 4; ++a0)
            #pragma unroll
            for (int a1 = 0; a1 < 4; ++a1) acc[a0][a1] = 0.f;

        #pragma unroll 8
        for (int s = 0; s < sBound; ++s) {
            const float4 wv = *(const float4*)&sW[IDX(s, 4 * j)];
            const float4 xv = *(const float4*)&sX[IDXX(s, 4 * i)];
            acc[0][0] = fmaf(wv.x, xv.x, acc[0][0]);
            acc[0][1] = fmaf(wv.x, xv.y, acc[0][1]);
            acc[0][2] = fmaf(wv.x, xv.z, acc[0][2]);
            acc[0][3] = fmaf(wv.x, xv.w, acc[0][3]);
            acc[1][0] = fmaf(wv.y, xv.x, acc[1][0]);
            acc[1][1] = fmaf(wv.y, xv.y, acc[1][1]);
            acc[1][2] = fmaf(wv.y, xv.z, acc[1][2]);
            acc[1][3] = fmaf(wv.y, xv.w, acc[1][3]);
            acc[2][0] = fmaf(wv.z, xv.x, acc[2][0]);
            acc[2][1] = fmaf(wv.z, xv.y, acc[2][1]);
            acc[2][2] = fmaf(wv.z, xv.z, acc[2][2]);
            acc[2][3] = fmaf(wv.z, xv.w, acc[2][3]);
            acc[3][0] = fmaf(wv.w, xv.x, acc[3][0]);
            acc[3][1] = fmaf(wv.w, xv.y, acc[3][1]);
            acc[3][2] = fmaf(wv.w, xv.z, acc[3][2]);
            acc[3][3] = fmaf(wv.w, xv.w, acc[3][3]);
        }
        #pragma unroll
        for (int tj = 0; tj < 4; ++tj) {
            const int t = 4 * j + tj;
            float* yrow = y + (((size_t)b * TLEN + t0 + t) * NH + hh) * PP;
            *(float4*)(yrow + 4 * i) =
                make_float4(acc[tj][0], acc[tj][1], acc[tj][2], acc[tj][3]);
        }
    }
}

// ---------------------------------------------------------------------------
// K2: cross-chunk scan, one thread per (bh, p, n-pair). hlast RMW adds A31*H0[31].
// ---------------------------------------------------------------------------
__global__ __launch_bounds__(256) void k2_scan(float* __restrict__ hlast) // [B,H,P,N]
{
    const int idx = blockIdx.x * 256 + threadIdx.x;   // bh*(PP*NN/2) + pn2
    const int bh  = idx >> 11;
    const int pn2 = idx & 2047;

    float2 h = make_float2(0.f, 0.f);
    #pragma unroll
    for (int c = 0; c < NCH; ++c) {
        const size_t off = ((size_t)bh * NCH + c) * (PP * NN / 2) + pn2;
        g_H0[off] = __floats2half2_rn(h.x, h.y);
        if (c < NCH - 1) {
            const float A = g_A[bh * NCH + c];
            const float2 s = __half22float2(g_S[off]);
            h.x = fmaf(A, h.x, s.x);
            h.y = fmaf(A, h.y, s.y);
        }
    }
    // h == H0[31]; hlast already holds fp32 S31 from kA
    const float A31 = g_A[bh * NCH + (NCH - 1)];
    float2* hp = (float2*)hlast + (size_t)bh * (PP * NN / 2) + pn2;
    float2 v = *hp;
    v.x = fmaf(A31, h.x, v.x);
    v.y = fmaf(A31, h.y, v.y);
    *hp = v;
}

// ---------------------------------------------------------------------------
// KC: inter-chunk correction. One block per (b,h,c).
//   y[t,p] += a_t * sum_n C[t,n] H0[p,n]   (H0 from fp16)
// ---------------------------------------------------------------------------
__global__ __launch_bounds__(256) void kC_corr(
    const float* __restrict__ Cm,
    float* __restrict__ y)
{
    extern __shared__ float smem[];
    float* sC  = smem;                // [CHL][LDS_]
    float* sH  = sC + CHL * LDS_;     // [PP][LDS_]  -> later sY2[t][p]
    float* sY2 = sH;

    __shared__ float sh_a[CHL];

    const int blk = blockIdx.x;
    const int c  = blk % NCH;
    const int hh = (blk / NCH) % NH;
    const int b  = blk / (NCH * NH);
    const int t0 = c * CHL;
    const int tid = threadIdx.x;

    if (tid < CHL) sh_a[tid] = g_a[(size_t)blk * CHL + tid];
    for (int i = tid; i < CHL * NN / 4; i += 256) {
        const int r = i >> 4, q = i & 15;
        cp16(&sC[IDX(r, q * 4)], (const float4*)(Cm + ((size_t)b * TLEN + t0 + r) * NN) + q);
    }
    {
        const __half2* Hp = g_H0 + (size_t)blk * (PP * NN / 2);
        for (int i = tid; i < PP * NN / 2; i += 256) {
            const int r = i >> 5, q = i & 31;           // NN/2 = 32 half2 per row
            *(float2*)&sH[IDX(r, 2 * q)] = __half22float2(Hp[i]);
        }
    }
    cp_commit_wait();
    __syncthreads();

    const int i = tid & 15;
    const int j = tid >> 4;

    // GEMM3: Y2[t,p] = sum_n C[t,n] H0[p,n]; t = j+16tj, p = i+16pi
    float acc2[4][4];
    #pragma unroll
    for (int a0 = 0; a0 < 4; ++a0)
        #pragma unroll
        for (int a1 = 0; a1 < 4; ++a1) acc2[a0][a1] = 0.f;

    #pragma unroll 4
    for (int n4 = 0; n4 < NN / 4; ++n4) {
        float4 cv[4], hv[4];
        #pragma unroll
        for (int tj = 0; tj < 4; ++tj) cv[tj] = *(const float4*)&sC[IDX(j + 16 * tj, n4 * 4)];
        #pragma unroll
        for (int pi = 0; pi < 4; ++pi) hv[pi] = *(const float4*)&sH[IDX(i + 16 * pi, n4 * 4)];
        #pragma unroll
        for (int tj = 0; tj < 4; ++tj)
            #pragma unroll
            for (int pi = 0; pi < 4; ++pi) {
                acc2[tj][pi] = fmaf(cv[tj].x, hv[pi].x, acc2[tj][pi]);
                acc2[tj][pi] = fmaf(cv[tj].y, hv[pi].y, acc2[tj][pi]);
                acc2[tj][pi] = fmaf(cv[tj].z, hv[pi].z, acc2[tj][pi]);
                acc2[tj][pi] = fmaf(cv[tj].w, hv[pi].w, acc2[tj][pi]);
            }
    }
    __syncthreads();   // GEMM3 reads of sH done before sY2 overwrites it

    #pragma unroll
    for (int tj = 0; tj < 4; ++tj) {
        const int t = j + 16 * tj;
        const float at = sh_a[t];
        #pragma unroll
        for (int pi = 0; pi < 4; ++pi)
            sY2[IDX(t, i + 16 * pi)] = at * acc2[tj][pi];
    }
    __syncthreads();

    // float4 read-modify-write of y (L2-resident)
    #pragma unroll
    for (int tj = 0; tj < 4; ++tj) {
        const int t = 4 * j + tj;
        const float4 yv2 = *(const float4*)&sY2[IDX(t, 4 * i)];
        float* yrow = y + (((size_t)b * TLEN + t0 + t) * NH + hh) * PP;
        float4 v = *(const float4*)(yrow + 4 * i);
        v.x += yv2.x; v.y += yv2.y; v.z += yv2.z; v.w += yv2.w;
        *(float4*)(yrow + 4 * i) = v;
    }
}

extern "C" void kernel_launch(void* const* d_in, const int* in_sizes, int n_in,
                              void* d_out, int out_size) {
    const float* X     = (const float*)d_in[0];
    const float* delta = (const float*)d_in[1];
    const float* Bm    = (const float*)d_in[2];
    const float* Cm    = (const float*)d_in[3];
    const float* A_log = (const float*)d_in[4];

    float* y     = (float*)d_out;
    float* hlast = y + (size_t)BSZ * TLEN * NH * PP;

    const int kA_smem = (2 * CHL * LDS_ + CHL * NN) * (int)sizeof(float);  // 51200 B
    const int kC_smem = 2 * CHL * LDS_ * (int)sizeof(float);               // 34816 B
    cudaFuncSetAttribute(kA_intra, cudaFuncAttributeMaxDynamicSharedMemorySize, kA_smem);
    cudaFuncSetAttribute(kC_corr,  cudaFuncAttributeMaxDynamicSharedMemorySize, kC_smem);

    kA_intra<<<BSZ * NH * NCH, 256, kA_smem>>>(X, delta, Bm, Cm, A_log, y, hlast); // 1024 blocks
    k2_scan<<<(BSZ * NH * PP * NN / 2) / 256, 256>>>(hlast);                       // 256 blocks
    kC_corr<<<BSZ * NH * NCH, 256, kC_smem>>>(Cm, y);                              // 1024 blocks
}

// round 14
// speedup vs baseline: 1.5469x; 1.5469x over previous
#include <cuda_runtime.h>
#include <cuda_fp16.h>

#define BSZ 2
#define TLEN 2048
#define NH 16
#define PP 64
#define NN 64
#define CHL 64                 // chunk length
#define NCH (TLEN / CHL)       // 32 chunks
#define LDS_ (NN + 4)          // padded row stride (68)
#define IDX(r,c) ((r) * LDS_ + (c))

// Scratch (device globals; allocation-free). State scratch in fp16 (half traffic).
__device__ __half2 g_S [BSZ * NH * NCH * PP * NN / 2];  // per-chunk local state
__device__ __half2 g_H0[BSZ * NH * NCH * PP * NN / 2];  // state entering chunk
__device__ float   g_A [BSZ * NH * NCH];                // per-chunk total decay
__device__ float   g_a [BSZ * NH * NCH * CHL];          // a_t = exp(negA*cum_t)

// ---------------------------------------------------------------------------
// KA: fused intra-chunk kernel. One block per (b,h,c), 256 threads.
// 3 smem buffers (sW aliases sC after GEMM1): 52224 B -> 4 blocks/SM.
//   GEMM1 : G[t,s]  = sum_n C[t,n] B[s,n]
//   W^T   : sW[s,t] = (s<=t) ? exp(negA*(cum_t-cum_s))*delta_s*G : 0
//   GEMM-S: S[p,n]  = sum_s r_s B[s,n] X[s,p]  -> g_S fp16; chunk 31 also -> hlast fp32
//   GEMM2 : y[t,p]  = sum_{s<=t} W[t,s] X[s,p]
// ---------------------------------------------------------------------------
__global__ __launch_bounds__(256) void kA_intra(
    const float* __restrict__ X,      // [B,T,H,P]
    const float* __restrict__ delta,  // [B,T,H]
    const float* __restrict__ Bm,     // [B,T,N]
    const float* __restrict__ Cm,     // [B,T,N]
    const float* __restrict__ A_log,  // [H]
    float* __restrict__ y,            // [B,T,H,P]
    float* __restrict__ hlast)        // [B,H,P,N]
{
    extern __shared__ float smem[];
    float* sB = smem;                 // [CHL][LDS_] raw B, later scaled by r_s
    float* sC = sB + CHL * LDS_;      // [CHL][LDS_] C, later W^T (sW aliases it)
    float* sX = sC + CHL * LDS_;      // [CHL][LDS_]
    float* sW = sC;                   // alias: W transposed sW[s][t]

    __shared__ float sh_d[CHL], sh_cum[CHL], sh_r[CHL];
    __shared__ float sh_wsum[2];

    const int blk = blockIdx.x;            // (b*NH+h)*NCH + c
    const int c  = blk % NCH;
    const int hh = (blk / NCH) % NH;
    const int b  = blk / (NCH * NH);
    const int t0 = c * CHL;
    const int tid = threadIdx.x;
    const int lane = tid & 31;

    const float negA = -__expf(A_log[hh]);

    // ---- stage delta + warp-level inclusive scan (phase 1) ----
    if (tid < CHL) {
        const float d = __ldg(delta + ((size_t)b * TLEN + t0 + tid) * NH + hh);
        sh_d[tid] = d;
        float v = d;
        #pragma unroll
        for (int off = 1; off < 32; off <<= 1) {
            const float t = __shfl_up_sync(0xffffffffu, v, off);
            if (lane >= off) v += t;
        }
        sh_cum[tid] = v;
        if (lane == 31) sh_wsum[tid >> 5] = v;
    }

    // ---- stage B, C, X (LDG -> STS; L1-cached, B/C shared across heads) ----
    for (int i = tid; i < CHL * NN / 4; i += 256) {
        const int r = i >> 4, q = i & 15;
        *(float4*)&sB[IDX(r, q * 4)] =
            __ldg((const float4*)(Bm + ((size_t)b * TLEN + t0 + r) * NN) + q);
        *(float4*)&sC[IDX(r, q * 4)] =
            __ldg((const float4*)(Cm + ((size_t)b * TLEN + t0 + r) * NN) + q);
    }
    for (int i = tid; i < CHL * PP / 4; i += 256) {
        const int r = i >> 4, q = i & 15;
        *(float4*)&sX[IDX(r, q * 4)] =
            __ldg((const float4*)(X + (((size_t)b * TLEN + t0 + r) * NH + hh) * PP) + q);
    }
    __syncthreads();   // sync1: staging + scan phase1 done

    // ---- scan phase 2: cross-warp fixup, r_s, a_t, A_c ----
    if (tid < CHL) {
        const float cum = sh_cum[tid] + (tid >= 32 ? sh_wsum[0] : 0.f);
        sh_cum[tid] = cum;
        const float cumTot = sh_wsum[0] + sh_wsum[1];
        g_a[(size_t)blk * CHL + tid] = __expf(negA * cum);
        sh_r[tid] = __expf(negA * (cumTot - cum)) * sh_d[tid];
        if (tid == 0) g_A[blk] = __expf(negA * cumTot);
    }

    const int i = tid & 15;
    const int j = tid >> 4;

    // ---- GEMM1: G[t,s], t = j+16tj, s = i+16si, reduce over n ----
    float g[4][4];
    #pragma unroll
    for (int a0 = 0; a0 < 4; ++a0)
        #pragma unroll
        for (int a1 = 0; a1 < 4; ++a1) g[a0][a1] = 0.f;

    #pragma unroll 4
    for (int n4 = 0; n4 < NN / 4; ++n4) {
        float4 cv[4], bv[4];
        #pragma unroll
        for (int tj = 0; tj < 4; ++tj) cv[tj] = *(const float4*)&sC[IDX(j + 16 * tj, n4 * 4)];
        #pragma unroll
        for (int si = 0; si < 4; ++si) bv[si] = *(const float4*)&sB[IDX(i + 16 * si, n4 * 4)];
        #pragma unroll
        for (int tj = 0; tj < 4; ++tj)
            #pragma unroll
            for (int si = 0; si < 4; ++si) {
                g[tj][si] = fmaf(cv[tj].x, bv[si].x, g[tj][si]);
                g[tj][si] = fmaf(cv[tj].y, bv[si].y, g[tj][si]);
                g[tj][si] = fmaf(cv[tj].z, bv[si].z, g[tj][si]);
                g[tj][si] = fmaf(cv[tj].w, bv[si].w, g[tj][si]);
            }
    }
    __syncthreads();   // sync2: GEMM1 reads of sB/sC done; sh_cum finalized

    // ---- write W transposed into sC's space ----
    #pragma unroll
    for (int tj = 0; tj < 4; ++tj) {
        const int t = j + 16 * tj;
        const float ct = sh_cum[t];
        #pragma unroll
        for (int si = 0; si < 4; ++si) {
            const int s = i + 16 * si;
            const float arg = negA * (ct - sh_cum[s]);
            const float e = __expf(fminf(arg, 0.f));
            sW[IDX(s, t)] = (s <= t) ? e * sh_d[s] * g[tj][si] : 0.f;
        }
    }
    // ---- scale sB in place by r_s ----
    for (int idx = tid; idx < CHL * NN / 4; idx += 256) {
        const int r = idx >> 4, q = idx & 15;
        float4 v = *(float4*)&sB[IDX(r, q * 4)];
        const float rr = sh_r[r];
        v.x *= rr; v.y *= rr; v.z *= rr; v.w *= rr;
        *(float4*)&sB[IDX(r, q * 4)] = v;
    }
    __syncthreads();   // sync3: sW and scaled sB visible

    // ---- GEMM-S: S[p][n] = sum_s sB'[s,n] sX[s,p]; n=4i.., p=4j.. ----
    {
        float acc[4][4];   // [pj][ni]
        #pragma unroll
        for (int a0 = 0; a0 < 4; ++a0)
            #pragma unroll
            for (int a1 = 0; a1 < 4; ++a1) acc[a0][a1] = 0.f;

        #pragma unroll 8
        for (int s = 0; s < CHL; ++s) {
            const float4 bv = *(const float4*)&sB[IDX(s, 4 * i)];
            const float4 xv = *(const float4*)&sX[IDX(s, 4 * j)];
            acc[0][0] = fmaf(xv.x, bv.x, acc[0][0]);
            acc[0][1] = fmaf(xv.x, bv.y, acc[0][1]);
            acc[0][2] = fmaf(xv.x, bv.z, acc[0][2]);
            acc[0][3] = fmaf(xv.x, bv.w, acc[0][3]);
            acc[1][0] = fmaf(xv.y, bv.x, acc[1][0]);
            acc[1][1] = fmaf(xv.y, bv.y, acc[1][1]);
            acc[1][2] = fmaf(xv.y, bv.z, acc[1][2]);
            acc[1][3] = fmaf(xv.y, bv.w, acc[1][3]);
            acc[2][0] = fmaf(xv.z, bv.x, acc[2][0]);
            acc[2][1] = fmaf(xv.z, bv.y, acc[2][1]);
            acc[2][2] = fmaf(xv.z, bv.z, acc[2][2]);
            acc[2][3] = fmaf(xv.z, bv.w, acc[2][3]);
            acc[3][0] = fmaf(xv.w, bv.x, acc[3][0]);
            acc[3][1] = fmaf(xv.w, bv.y, acc[3][1]);
            acc[3][2] = fmaf(xv.w, bv.z, acc[3][2]);
            acc[3][3] = fmaf(xv.w, bv.w, acc[3][3]);
        }
        // fp16 store of S (8B per store, coalesced)
        __half2* Sp = g_S + (size_t)blk * (PP * NN / 2);
        #pragma unroll
        for (int pj = 0; pj < 4; ++pj) {
            const int p = 4 * j + pj;
            __half2 h01 = __floats2half2_rn(acc[pj][0], acc[pj][1]);
            __half2 h23 = __floats2half2_rn(acc[pj][2], acc[pj][3]);
            uint2 u;
            u.x = *(unsigned*)&h01;
            u.y = *(unsigned*)&h23;
            *(uint2*)(Sp + p * (NN / 2) + 2 * i) = u;
        }
        // chunk 31: exact fp32 S -> hlast (K2 RMW-adds the tiny A31*H0 term)
        if (c == NCH - 1) {
            float* hp = hlast + ((size_t)(b * NH + hh)) * PP * NN;
            #pragma unroll
            for (int pj = 0; pj < 4; ++pj) {
                const int p = 4 * j + pj;
                *(float4*)(hp + p * NN + 4 * i) =
                    make_float4(acc[pj][0], acc[pj][1], acc[pj][2], acc[pj][3]);
            }
        }
    }

    // ---- GEMM2: Y1[t,p] = sum_{s<=t} W[t,s] X[s,p]; t=4j.., p=4i.. ----
    {
        const int sBound = ((tid >> 5) + 1) * 8;   // warp-uniform triangular bound
        float acc[4][4];   // [tj][pi]
        #pragma unroll
        for (int a0 = 0; a0 < 4; ++a0)
            #pragma unroll
            for (int a1 = 0; a1 < 4; ++a1) acc[a0][a1] = 0.f;

        #pragma unroll 8
        for (int s = 0; s < sBound; ++s) {
            const float4 wv = *(const float4*)&sW[IDX(s, 4 * j)];
            const float4 xv = *(const float4*)&sX[IDX(s, 4 * i)];
            acc[0][0] = fmaf(wv.x, xv.x, acc[0][0]);
            acc[0][1] = fmaf(wv.x, xv.y, acc[0][1]);
            acc[0][2] = fmaf(wv.x, xv.z, acc[0][2]);
            acc[0][3] = fmaf(wv.x, xv.w, acc[0][3]);
            acc[1][0] = fmaf(wv.y, xv.x, acc[1][0]);
            acc[1][1] = fmaf(wv.y, xv.y, acc[1][1]);
            acc[1][2] = fmaf(wv.y, xv.z, acc[1][2]);
            acc[1][3] = fmaf(wv.y, xv.w, acc[1][3]);
            acc[2][0] = fmaf(wv.z, xv.x, acc[2][0]);
            acc[2][1] = fmaf(wv.z, xv.y, acc[2][1]);
            acc[2][2] = fmaf(wv.z, xv.z, acc[2][2]);
            acc[2][3] = fmaf(wv.z, xv.w, acc[2][3]);
            acc[3][0] = fmaf(wv.w, xv.x, acc[3][0]);
            acc[3][1] = fmaf(wv.w, xv.y, acc[3][1]);
            acc[3][2] = fmaf(wv.w, xv.z, acc[3][2]);
            acc[3][3] = fmaf(wv.w, xv.w, acc[3][3]);
        }
        #pragma unroll
        for (int tj = 0; tj < 4; ++tj) {
            const int t = 4 * j + tj;
            float* yrow = y + (((size_t)b * TLEN + t0 + t) * NH + hh) * PP;
            *(float4*)(yrow + 4 * i) =
                make_float4(acc[tj][0], acc[tj][1], acc[tj][2], acc[tj][3]);
        }
    }
}

// ---------------------------------------------------------------------------
// K2: cross-chunk scan, one thread per (bh, p, n-pair). hlast RMW adds A31*H0[31].
// ---------------------------------------------------------------------------
__global__ __launch_bounds__(256) void k2_scan(float* __restrict__ hlast) // [B,H,P,N]
{
    const int idx = blockIdx.x * 256 + threadIdx.x;   // bh*(PP*NN/2) + pn2
    const int bh  = idx >> 11;
    const int pn2 = idx & 2047;

    float2 h = make_float2(0.f, 0.f);
    #pragma unroll
    for (int c = 0; c < NCH; ++c) {
        const size_t off = ((size_t)bh * NCH + c) * (PP * NN / 2) + pn2;
        g_H0[off] = __floats2half2_rn(h.x, h.y);
        if (c < NCH - 1) {
            const float A = g_A[bh * NCH + c];
            const float2 s = __half22float2(g_S[off]);
            h.x = fmaf(A, h.x, s.x);
            h.y = fmaf(A, h.y, s.y);
        }
    }
    // h == H0[31]; hlast already holds fp32 S31 from kA
    const float A31 = g_A[bh * NCH + (NCH - 1)];
    float2* hp = (float2*)hlast + (size_t)bh * (PP * NN / 2) + pn2;
    float2 v = *hp;
    v.x = fmaf(A31, h.x, v.x);
    v.y = fmaf(A31, h.y, v.y);
    *hp = v;
}

// ---------------------------------------------------------------------------
// KC: inter-chunk correction. One block per (b,h,c).
//   y[t,p] += a_t * sum_n C[t,n] H0[p,n]   (H0 from fp16)
// GEMM3 strided 4x4 tile; result staged via smem for float4 RMW of y.
// ---------------------------------------------------------------------------
__global__ __launch_bounds__(256) void kC_corr(
    const float* __restrict__ Cm,
    float* __restrict__ y)
{
    extern __shared__ float smem[];
    float* sC  = smem;                // [CHL][LDS_]
    float* sH  = sC + CHL * LDS_;     // [PP][LDS_]  -> later sY2[t][p]
    float* sY2 = sH;

    __shared__ float sh_a[CHL];

    const int blk = blockIdx.x;
    const int c  = blk % NCH;
    const int hh = (blk / NCH) % NH;
    const int b  = blk / (NCH * NH);
    const int t0 = c * CHL;
    const int tid = threadIdx.x;

    if (tid < CHL) sh_a[tid] = g_a[(size_t)blk * CHL + tid];
    for (int i = tid; i < CHL * NN / 4; i += 256) {
        const int r = i >> 4, q = i & 15;
        *(float4*)&sC[IDX(r, q * 4)] =
            __ldg((const float4*)(Cm + ((size_t)b * TLEN + t0 + r) * NN) + q);
    }
    {
        const __half2* Hp = g_H0 + (size_t)blk * (PP * NN / 2);
        for (int i = tid; i < PP * NN / 4; i += 256) {   // 2 half2 per iter
            const int r = i >> 4, q = i & 15;            // row r, half2-pair q
            const uint2 u = __ldg((const uint2*)(Hp + r * (NN / 2)) + q);
            const float2 f01 = __half22float2(*(const __half2*)&u.x);
            const float2 f23 = __half22float2(*(const __half2*)&u.y);
            *(float4*)&sH[IDX(r, q * 4)] = make_float4(f01.x, f01.y, f23.x, f23.y);
        }
    }
    __syncthreads();

    const int i = tid & 15;
    const int j = tid >> 4;

    // GEMM3: Y2[t,p] = sum_n C[t,n] H0[p,n]; t = j+16tj, p = i+16pi
    float acc2[4][4];
    #pragma unroll
    for (int a0 = 0; a0 < 4; ++a0)
        #pragma unroll
        for (int a1 = 0; a1 < 4; ++a1) acc2[a0][a1] = 0.f;

    #pragma unroll 4
    for (int n4 = 0; n4 < NN / 4; ++n4) {
        float4 cv[4], hv[4];
        #pragma unroll
        for (int tj = 0; tj < 4; ++tj) cv[tj] = *(const float4*)&sC[IDX(j + 16 * tj, n4 * 4)];
        #pragma unroll
        for (int pi = 0; pi < 4; ++pi) hv[pi] = *(const float4*)&sH[IDX(i + 16 * pi, n4 * 4)];
        #pragma unroll
        for (int tj = 0; tj < 4; ++tj)
            #pragma unroll
            for (int pi = 0; pi < 4; ++pi) {
                acc2[tj][pi] = fmaf(cv[tj].x, hv[pi].x, acc2[tj][pi]);
                acc2[tj][pi] = fmaf(cv[tj].y, hv[pi].y, acc2[tj][pi]);
                acc2[tj][pi] = fmaf(cv[tj].z, hv[pi].z, acc2[tj][pi]);
                acc2[tj][pi] = fmaf(cv[tj].w, hv[pi].w, acc2[tj][pi]);
            }
    }
    __syncthreads();   // GEMM3 reads of sH done before sY2 overwrites it

    #pragma unroll
    for (int tj = 0; tj < 4; ++tj) {
        const int t = j + 16 * tj;
        const float at = sh_a[t];
        #pragma unroll
        for (int pi = 0; pi < 4; ++pi)
            sY2[IDX(t, i + 16 * pi)] = at * acc2[tj][pi];
    }
    __syncthreads();

    // float4 read-modify-write of y (L2-resident)
    #pragma unroll
    for (int tj = 0; tj < 4; ++tj) {
        const int t = 4 * j + tj;
        const float4 yv2 = *(const float4*)&sY2[IDX(t, 4 * i)];
        float* yrow = y + (((size_t)b * TLEN + t0 + t) * NH + hh) * PP;
        float4 v = *(const float4*)(yrow + 4 * i);
        v.x += yv2.x; v.y += yv2.y; v.z += yv2.z; v.w += yv2.w;
        *(float4*)(yrow + 4 * i) = v;
    }
}

extern "C" void kernel_launch(void* const* d_in, const int* in_sizes, int n_in,
                              void* d_out, int out_size) {
    const float* X     = (const float*)d_in[0];
    const float* delta = (const float*)d_in[1];
    const float* Bm    = (const float*)d_in[2];
    const float* Cm    = (const float*)d_in[3];
    const float* A_log = (const float*)d_in[4];

    float* y     = (float*)d_out;
    float* hlast = y + (size_t)BSZ * TLEN * NH * PP;

    const int kA_smem = 3 * CHL * LDS_ * (int)sizeof(float);  // 52224 B -> 4 blocks/SM
    const int kC_smem = 2 * CHL * LDS_ * (int)sizeof(float);  // 34816 B
    cudaFuncSetAttribute(kA_intra, cudaFuncAttributeMaxDynamicSharedMemorySize, kA_smem);
    cudaFuncSetAttribute(kC_corr,  cudaFuncAttributeMaxDynamicSharedMemorySize, kC_smem);

    kA_intra<<<BSZ * NH * NCH, 256, kA_smem>>>(X, delta, Bm, Cm, A_log, y, hlast); // 1024 blocks
    k2_scan<<<(BSZ * NH * PP * NN / 2) / 256, 256>>>(hlast);                       // 256 blocks
    kC_corr<<<BSZ * NH * NCH, 256, kC_smem>>>(Cm, y);                              // 1024 blocks
}

// round 15
// speedup vs baseline: 1.7250x; 1.1151x over previous
#include <cuda_runtime.h>
#include <cuda_fp16.h>

#define BSZ 2
#define TLEN 2048
#define NH 16
#define PP 64
#define NN 64
#define CHL 64                 // chunk length
#define NCH (TLEN / CHL)       // 32 chunks
#define LDS_ (NN + 4)          // padded row stride (68)
#define IDX(r,c) ((r) * LDS_ + (c))

// Scratch (device globals; allocation-free).
__device__ __half2 g_S [BSZ * NH * NCH * PP * NN / 2];  // per-chunk local state
__device__ __half2 g_H0[BSZ * NH * NCH * PP * NN / 2];  // state entering chunk
__device__ float   g_A [BSZ * NH * NCH];                // per-chunk total decay
__device__ float   g_a [BSZ * NH * NCH * CHL];          // a_t = exp(negA*cum_t)
__device__ float   g_Gt[BSZ * NCH * CHL * NN];          // G^T[b][c][s][t] (head-shared)

// ---------------------------------------------------------------------------
// KG: head-shared Gram matrix, one block per (b,c) (64 blocks).
//   G[t,s] = sum_n C[t,n] B[s,n]; stored TRANSPOSED: g_Gt[b][c][s][t].
// Strided 4x4 tile GEMM; result staged via smem for coalesced float4 writeback.
// ---------------------------------------------------------------------------
__global__ __launch_bounds__(256) void kG_bc(
    const float* __restrict__ Bm,     // [B,T,N]
    const float* __restrict__ Cm)     // [B,T,N]
{
    extern __shared__ float smem[];
    float* sB  = smem;                // [CHL][LDS_]
    float* sC  = sB + CHL * LDS_;
    float* sGT = sC + CHL * LDS_;     // [CHL][LDS_] G^T staging

    const int blk = blockIdx.x;       // b*NCH + c
    const int c = blk % NCH;
    const int b = blk / NCH;
    const int t0 = c * CHL;
    const int tid = threadIdx.x;

    for (int i = tid; i < CHL * NN / 4; i += 256) {
        const int r = i >> 4, q = i & 15;
        *(float4*)&sB[IDX(r, q * 4)] =
            __ldg((const float4*)(Bm + ((size_t)b * TLEN + t0 + r) * NN) + q);
        *(float4*)&sC[IDX(r, q * 4)] =
            __ldg((const float4*)(Cm + ((size_t)b * TLEN + t0 + r) * NN) + q);
    }
    __syncthreads();

    const int i = tid & 15;
    const int j = tid >> 4;

    // G[t,s]: t = j+16tj, s = i+16si, reduce over n
    float g[4][4];
    #pragma unroll
    for (int a0 = 0; a0 < 4; ++a0)
        #pragma unroll
        for (int a1 = 0; a1 < 4; ++a1) g[a0][a1] = 0.f;

    #pragma unroll 4
    for (int n4 = 0; n4 < NN / 4; ++n4) {
        float4 cv[4], bv[4];
        #pragma unroll
        for (int tj = 0; tj < 4; ++tj) cv[tj] = *(const float4*)&sC[IDX(j + 16 * tj, n4 * 4)];
        #pragma unroll
        for (int si = 0; si < 4; ++si) bv[si] = *(const float4*)&sB[IDX(i + 16 * si, n4 * 4)];
        #pragma unroll
        for (int tj = 0; tj < 4; ++tj)
            #pragma unroll
            for (int si = 0; si < 4; ++si) {
                g[tj][si] = fmaf(cv[tj].x, bv[si].x, g[tj][si]);
                g[tj][si] = fmaf(cv[tj].y, bv[si].y, g[tj][si]);
                g[tj][si] = fmaf(cv[tj].z, bv[si].z, g[tj][si]);
                g[tj][si] = fmaf(cv[tj].w, bv[si].w, g[tj][si]);
            }
    }

    // stage transposed into sGT[s][t]
    #pragma unroll
    for (int si = 0; si < 4; ++si) {
        const int s = i + 16 * si;
        #pragma unroll
        for (int tj = 0; tj < 4; ++tj)
            sGT[IDX(s, j + 16 * tj)] = g[tj][si];
    }
    __syncthreads();

    // coalesced float4 writeback
    float* Gp = g_Gt + (size_t)blk * (CHL * NN);
    for (int idx = tid; idx < CHL * NN / 4; idx += 256) {
        const int r = idx >> 4, q = idx & 15;
        *(float4*)(Gp + r * NN + 4 * q) = *(const float4*)&sGT[IDX(r, 4 * q)];
    }
}

// ---------------------------------------------------------------------------
// KA: fused intra-chunk kernel. One block per (b,h,c), 256 threads.
// 3 smem buffers: sB, sW (staged from g_Gt, transformed in place), sX.
//   W^T   : sW[s,t] = (s<=t) ? exp(negA*(cum_t-cum_s))*delta_s*G^T[s,t] : 0
//   GEMM-S: S[p,n]  = sum_s r_s B[s,n] X[s,p]  -> g_S fp16; chunk 31 also -> hlast fp32
//   GEMM2 : y[t,p]  = sum_{s<=t} W[t,s] X[s,p]
// ---------------------------------------------------------------------------
__global__ __launch_bounds__(256) void kA_intra(
    const float* __restrict__ X,      // [B,T,H,P]
    const float* __restrict__ delta,  // [B,T,H]
    const float* __restrict__ Bm,     // [B,T,N]
    const float* __restrict__ A_log,  // [H]
    float* __restrict__ y,            // [B,T,H,P]
    float* __restrict__ hlast)        // [B,H,P,N]
{
    extern __shared__ float smem[];
    float* sB = smem;                 // [CHL][LDS_] raw B, later scaled by r_s
    float* sW = sB + CHL * LDS_;      // [CHL][LDS_] G^T, then W^T (in place)
    float* sX = sW + CHL * LDS_;      // [CHL][LDS_]

    __shared__ float sh_d[CHL], sh_cum[CHL], sh_r[CHL];
    __shared__ float sh_wsum[2];

    const int blk = blockIdx.x;            // (b*NH+h)*NCH + c
    const int c  = blk % NCH;
    const int hh = (blk / NCH) % NH;
    const int b  = blk / (NCH * NH);
    const int t0 = c * CHL;
    const int tid = threadIdx.x;
    const int lane = tid & 31;

    const float negA = -__expf(A_log[hh]);

    // ---- stage delta + warp-level inclusive scan (phase 1) ----
    if (tid < CHL) {
        const float d = __ldg(delta + ((size_t)b * TLEN + t0 + tid) * NH + hh);
        sh_d[tid] = d;
        float v = d;
        #pragma unroll
        for (int off = 1; off < 32; off <<= 1) {
            const float t = __shfl_up_sync(0xffffffffu, v, off);
            if (lane >= off) v += t;
        }
        sh_cum[tid] = v;
        if (lane == 31) sh_wsum[tid >> 5] = v;
    }

    // ---- stage B, G^T, X (LDG -> STS; B and G^T L2-shared across heads) ----
    {
        const float* Gp = g_Gt + ((size_t)b * NCH + c) * (CHL * NN);
        for (int i = tid; i < CHL * NN / 4; i += 256) {
            const int r = i >> 4, q = i & 15;
            *(float4*)&sB[IDX(r, q * 4)] =
                __ldg((const float4*)(Bm + ((size_t)b * TLEN + t0 + r) * NN) + q);
            *(float4*)&sW[IDX(r, q * 4)] =
                __ldg((const float4*)(Gp + r * NN) + q);
            *(float4*)&sX[IDX(r, q * 4)] =
                __ldg((const float4*)(X + (((size_t)b * TLEN + t0 + r) * NH + hh) * PP) + q);
        }
    }
    __syncthreads();   // sync1: staging + scan phase1 done

    // ---- scan phase 2: cross-warp fixup, r_s, a_t, A_c ----
    if (tid < CHL) {
        const float cum = sh_cum[tid] + (tid >= 32 ? sh_wsum[0] : 0.f);
        sh_cum[tid] = cum;
        const float cumTot = sh_wsum[0] + sh_wsum[1];
        g_a[(size_t)blk * CHL + tid] = __expf(negA * cum);
        sh_r[tid] = __expf(negA * (cumTot - cum)) * sh_d[tid];
        if (tid == 0) g_A[blk] = __expf(negA * cumTot);
    }
    __syncthreads();   // sync2: sh_cum/sh_r finalized

    const int i = tid & 15;
    const int j = tid >> 4;

    // ---- W transform in place: sW[s][t] *= mask*exp*delta_s ----
    // thread: rows s = 4j+sj, cols t = 4i..4i+3 (float4, conflict-free)
    {
        const float ct0 = sh_cum[4 * i + 0];
        const float ct1 = sh_cum[4 * i + 1];
        const float ct2 = sh_cum[4 * i + 2];
        const float ct3 = sh_cum[4 * i + 3];
        #pragma unroll
        for (int sj = 0; sj < 4; ++sj) {
            const int s = 4 * j + sj;
            const float cs = sh_cum[s];
            const float ds = sh_d[s];
            float4 w = *(const float4*)&sW[IDX(s, 4 * i)];
            w.x = (s <= 4 * i + 0) ? __expf(fminf(negA * (ct0 - cs), 0.f)) * ds * w.x : 0.f;
            w.y = (s <= 4 * i + 1) ? __expf(fminf(negA * (ct1 - cs), 0.f)) * ds * w.y : 0.f;
            w.z = (s <= 4 * i + 2) ? __expf(fminf(negA * (ct2 - cs), 0.f)) * ds * w.z : 0.f;
            w.w = (s <= 4 * i + 3) ? __expf(fminf(negA * (ct3 - cs), 0.f)) * ds * w.w : 0.f;
            *(float4*)&sW[IDX(s, 4 * i)] = w;
        }
    }
    // ---- scale sB in place by r_s ----
    for (int idx = tid; idx < CHL * NN / 4; idx += 256) {
        const int r = idx >> 4, q = idx & 15;
        float4 v = *(float4*)&sB[IDX(r, q * 4)];
        const float rr = sh_r[r];
        v.x *= rr; v.y *= rr; v.z *= rr; v.w *= rr;
        *(float4*)&sB[IDX(r, q * 4)] = v;
    }
    __syncthreads();   // sync3: sW and scaled sB visible

    // ---- GEMM-S: S[p][n] = sum_s sB'[s,n] sX[s,p]; n=4i.., p=4j.. ----
    {
        float acc[4][4];   // [pj][ni]
        #pragma unroll
        for (int a0 = 0; a0 < 4; ++a0)
            #pragma unroll
            for (int a1 = 0; a1 < 4; ++a1) acc[a0][a1] = 0.f;

        #pragma unroll 8
        for (int s = 0; s < CHL; ++s) {
            const float4 bv = *(const float4*)&sB[IDX(s, 4 * i)];
            const float4 xv = *(const float4*)&sX[IDX(s, 4 * j)];
            acc[0][0] = fmaf(xv.x, bv.x, acc[0][0]);
            acc[0][1] = fmaf(xv.x, bv.y, acc[0][1]);
            acc[0][2] = fmaf(xv.x, bv.z, acc[0][2]);
            acc[0][3] = fmaf(xv.x, bv.w, acc[0][3]);
            acc[1][0] = fmaf(xv.y, bv.x, acc[1][0]);
            acc[1][1] = fmaf(xv.y, bv.y, acc[1][1]);
            acc[1][2] = fmaf(xv.y, bv.z, acc[1][2]);
            acc[1][3] = fmaf(xv.y, bv.w, acc[1][3]);
            acc[2][0] = fmaf(xv.z, bv.x, acc[2][0]);
            acc[2][1] = fmaf(xv.z, bv.y, acc[2][1]);
            acc[2][2] = fmaf(xv.z, bv.z, acc[2][2]);
            acc[2][3] = fmaf(xv.z, bv.w, acc[2][3]);
            acc[3][0] = fmaf(xv.w, bv.x, acc[3][0]);
            acc[3][1] = fmaf(xv.w, bv.y, acc[3][1]);
            acc[3][2] = fmaf(xv.w, bv.z, acc[3][2]);
            acc[3][3] = fmaf(xv.w, bv.w, acc[3][3]);
        }
        // fp16 store of S (8B per store, coalesced)
        __half2* Sp = g_S + (size_t)blk * (PP * NN / 2);
        #pragma unroll
        for (int pj = 0; pj < 4; ++pj) {
            const int p = 4 * j + pj;
            __half2 h01 = __floats2half2_rn(acc[pj][0], acc[pj][1]);
            __half2 h23 = __floats2half2_rn(acc[pj][2], acc[pj][3]);
            uint2 u;
            u.x = *(unsigned*)&h01;
            u.y = *(unsigned*)&h23;
            *(uint2*)(Sp + p * (NN / 2) + 2 * i) = u;
        }
        // chunk 31: exact fp32 S -> hlast (K2 RMW-adds the tiny A31*H0 term)
        if (c == NCH - 1) {
            float* hp = hlast + ((size_t)(b * NH + hh)) * PP * NN;
            #pragma unroll
            for (int pj = 0; pj < 4; ++pj) {
                const int p = 4 * j + pj;
                *(float4*)(hp + p * NN + 4 * i) =
                    make_float4(acc[pj][0], acc[pj][1], acc[pj][2], acc[pj][3]);
            }
        }
    }

    // ---- GEMM2: Y1[t,p] = sum_{s<=t} W[t,s] X[s,p]; t=4j.., p=4i.. ----
    {
        const int sBound = ((tid >> 5) + 1) * 8;   // warp-uniform triangular bound
        float acc[4][4];   // [tj][pi]
        #pragma unroll
        for (int a0 = 0; a0 < 4; ++a0)
            #pragma unroll
            for (int a1 = 0; a1 < 4; ++a1) acc[a0][a1] = 0.f;

        #pragma unroll 8
        for (int s = 0; s < sBound; ++s) {
            const float4 wv = *(const float4*)&sW[IDX(s, 4 * j)];
            const float4 xv = *(const float4*)&sX[IDX(s, 4 * i)];
            acc[0][0] = fmaf(wv.x, xv.x, acc[0][0]);
            acc[0][1] = fmaf(wv.x, xv.y, acc[0][1]);
            acc[0][2] = fmaf(wv.x, xv.z, acc[0][2]);
            acc[0][3] = fmaf(wv.x, xv.w, acc[0][3]);
            acc[1][0] = fmaf(wv.y, xv.x, acc[1][0]);
            acc[1][1] = fmaf(wv.y, xv.y, acc[1][1]);
            acc[1][2] = fmaf(wv.y, xv.z, acc[1][2]);
            acc[1][3] = fmaf(wv.y, xv.w, acc[1][3]);
            acc[2][0] = fmaf(wv.z, xv.x, acc[2][0]);
            acc[2][1] = fmaf(wv.z, xv.y, acc[2][1]);
            acc[2][2] = fmaf(wv.z, xv.z, acc[2][2]);
            acc[2][3] = fmaf(wv.z, xv.w, acc[2][3]);
            acc[3][0] = fmaf(wv.w, xv.x, acc[3][0]);
            acc[3][1] = fmaf(wv.w, xv.y, acc[3][1]);
            acc[3][2] = fmaf(wv.w, xv.z, acc[3][2]);
            acc[3][3] = fmaf(wv.w, xv.w, acc[3][3]);
        }
        #pragma unroll
        for (int tj = 0; tj < 4; ++tj) {
            const int t = 4 * j + tj;
            float* yrow = y + (((size_t)b * TLEN + t0 + t) * NH + hh) * PP;
            *(float4*)(yrow + 4 * i) =
                make_float4(acc[tj][0], acc[tj][1], acc[tj][2], acc[tj][3]);
        }
    }
}

// ---------------------------------------------------------------------------
// K2: cross-chunk scan, one thread per (bh, p, n-pair). hlast RMW adds A31*H0[31].
// ---------------------------------------------------------------------------
__global__ __launch_bounds__(256) void k2_scan(float* __restrict__ hlast) // [B,H,P,N]
{
    const int idx = blockIdx.x * 256 + threadIdx.x;   // bh*(PP*NN/2) + pn2
    const int bh  = idx >> 11;
    const int pn2 = idx & 2047;

    float2 h = make_float2(0.f, 0.f);
    #pragma unroll
    for (int c = 0; c < NCH; ++c) {
        const size_t off = ((size_t)bh * NCH + c) * (PP * NN / 2) + pn2;
        g_H0[off] = __floats2half2_rn(h.x, h.y);
        if (c < NCH - 1) {
            const float A = g_A[bh * NCH + c];
            const float2 s = __half22float2(g_S[off]);
            h.x = fmaf(A, h.x, s.x);
            h.y = fmaf(A, h.y, s.y);
        }
    }
    // h == H0[31]; hlast already holds fp32 S31 from kA
    const float A31 = g_A[bh * NCH + (NCH - 1)];
    float2* hp = (float2*)hlast + (size_t)bh * (PP * NN / 2) + pn2;
    float2 v = *hp;
    v.x = fmaf(A31, h.x, v.x);
    v.y = fmaf(A31, h.y, v.y);
    *hp = v;
}

// ---------------------------------------------------------------------------
// KC: inter-chunk correction. One block per (b,h,c).
//   y[t,p] += a_t * sum_n C[t,n] H0[p,n]   (H0 from fp16)
// ---------------------------------------------------------------------------
__global__ __launch_bounds__(256) void kC_corr(
    const float* __restrict__ Cm,
    float* __restrict__ y)
{
    extern __shared__ float smem[];
    float* sC  = smem;                // [CHL][LDS_]
    float* sH  = sC + CHL * LDS_;     // [PP][LDS_]  -> later sY2[t][p]
    float* sY2 = sH;

    __shared__ float sh_a[CHL];

    const int blk = blockIdx.x;
    const int c  = blk % NCH;
    const int hh = (blk / NCH) % NH;
    const int b  = blk / (NCH * NH);
    const int t0 = c * CHL;
    const int tid = threadIdx.x;

    if (tid < CHL) sh_a[tid] = g_a[(size_t)blk * CHL + tid];
    for (int i = tid; i < CHL * NN / 4; i += 256) {
        const int r = i >> 4, q = i & 15;
        *(float4*)&sC[IDX(r, q * 4)] =
            __ldg((const float4*)(Cm + ((size_t)b * TLEN + t0 + r) * NN) + q);
    }
    {
        const __half2* Hp = g_H0 + (size_t)blk * (PP * NN / 2);
        for (int i = tid; i < PP * NN / 4; i += 256) {   // 2 half2 per iter
            const int r = i >> 4, q = i & 15;
            const uint2 u = __ldg((const uint2*)(Hp + r * (NN / 2)) + q);
            const float2 f01 = __half22float2(*(const __half2*)&u.x);
            const float2 f23 = __half22float2(*(const __half2*)&u.y);
            *(float4*)&sH[IDX(r, q * 4)] = make_float4(f01.x, f01.y, f23.x, f23.y);
        }
    }
    __syncthreads();

    const int i = tid & 15;
    const int j = tid >> 4;

    // GEMM3: Y2[t,p] = sum_n C[t,n] H0[p,n]; t = j+16tj, p = i+16pi
    float acc2[4][4];
    #pragma unroll
    for (int a0 = 0; a0 < 4; ++a0)
        #pragma unroll
        for (int a1 = 0; a1 < 4; ++a1) acc2[a0][a1] = 0.f;

    #pragma unroll 4
    for (int n4 = 0; n4 < NN / 4; ++n4) {
        float4 cv[4], hv[4];
        #pragma unroll
        for (int tj = 0; tj < 4; ++tj) cv[tj] = *(const float4*)&sC[IDX(j + 16 * tj, n4 * 4)];
        #pragma unroll
        for (int pi = 0; pi < 4; ++pi) hv[pi] = *(const float4*)&sH[IDX(i + 16 * pi, n4 * 4)];
        #pragma unroll
        for (int tj = 0; tj < 4; ++tj)
            #pragma unroll
            for (int pi = 0; pi < 4; ++pi) {
                acc2[tj][pi] = fmaf(cv[tj].x, hv[pi].x, acc2[tj][pi]);
                acc2[tj][pi] = fmaf(cv[tj].y, hv[pi].y, acc2[tj][pi]);
                acc2[tj][pi] = fmaf(cv[tj].z, hv[pi].z, acc2[tj][pi]);
                acc2[tj][pi] = fmaf(cv[tj].w, hv[pi].w, acc2[tj][pi]);
            }
    }
    __syncthreads();   // GEMM3 reads of sH done before sY2 overwrites it

    #pragma unroll
    for (int tj = 0; tj < 4; ++tj) {
        const int t = j + 16 * tj;
        const float at = sh_a[t];
        #pragma unroll
        for (int pi = 0; pi < 4; ++pi)
            sY2[IDX(t, i + 16 * pi)] = at * acc2[tj][pi];
    }
    __syncthreads();

    // float4 read-modify-write of y (L2-resident)
    #pragma unroll
    for (int tj = 0; tj < 4; ++tj) {
        const int t = 4 * j + tj;
        const float4 yv2 = *(const float4*)&sY2[IDX(t, 4 * i)];
        float* yrow = y + (((size_t)b * TLEN + t0 + t) * NH + hh) * PP;
        float4 v = *(const float4*)(yrow + 4 * i);
        v.x += yv2.x; v.y += yv2.y; v.z += yv2.z; v.w += yv2.w;
        *(float4*)(yrow + 4 * i) = v;
    }
}

extern "C" void kernel_launch(void* const* d_in, const int* in_sizes, int n_in,
                              void* d_out, int out_size) {
    const float* X     = (const float*)d_in[0];
    const float* delta = (const float*)d_in[1];
    const float* Bm    = (const float*)d_in[2];
    const float* Cm    = (const float*)d_in[3];
    const float* A_log = (const float*)d_in[4];

    float* y     = (float*)d_out;
    float* hlast = y + (size_t)BSZ * TLEN * NH * PP;

    const int big_smem = 3 * CHL * LDS_ * (int)sizeof(float);  // 52224 B -> 4 blocks/SM
    const int kC_smem  = 2 * CHL * LDS_ * (int)sizeof(float);  // 34816 B
    cudaFuncSetAttribute(kG_bc,    cudaFuncAttributeMaxDynamicSharedMemorySize, big_smem);
    cudaFuncSetAttribute(kA_intra, cudaFuncAttributeMaxDynamicSharedMemorySize, big_smem);
    cudaFuncSetAttribute(kC_corr,  cudaFuncAttributeMaxDynamicSharedMemorySize, kC_smem);

    kG_bc<<<BSZ * NCH, 256, big_smem>>>(Bm, Cm);                                 // 64 blocks
    kA_intra<<<BSZ * NH * NCH, 256, big_smem>>>(X, delta, Bm, A_log, y, hlast);  // 1024 blocks
    k2_scan<<<(BSZ * NH * PP * NN / 2) / 256, 256>>>(hlast);                     // 256 blocks
    kC_corr<<<BSZ * NH * NCH, 256, kC_smem>>>(Cm, y);                            // 1024 blocks
}

// round 16
// speedup vs baseline: 1.9287x; 1.1181x over previous
#include <cuda_runtime.h>
#include <cuda_fp16.h>
#include <cstdint>

#define BSZ 2
#define TLEN 2048
#define NH 16
#define PP 64
#define NN 64
#define CHL 64                 // chunk length
#define NCH (TLEN / CHL)       // 32 chunks
#define LDS_ (NN + 4)          // padded row stride (68)
#define IDX(r,c) ((r) * LDS_ + (c))
#define HSTR 72                // fp16 tile row stride (144 B) - ldmatrix conflict-free

// Scratch (device globals; allocation-free).
__device__ __half2 g_S [BSZ * NH * NCH * PP * NN / 2];  // per-chunk local state
__device__ __half2 g_H0[BSZ * NH * NCH * PP * NN / 2];  // state entering chunk
__device__ float   g_A [BSZ * NH * NCH];                // per-chunk total decay
__device__ float   g_a [BSZ * NH * NCH * CHL];          // a_t = exp(negA*cum_t)
__device__ float   g_Gt[BSZ * NCH * CHL * NN];          // G^T[b][c][s][t] (head-shared)

__device__ __forceinline__ uint32_t sm_u32(const void* p) {
    return (uint32_t)__cvta_generic_to_shared(p);
}
__device__ __forceinline__ void ldsm_x4(uint32_t& r0, uint32_t& r1, uint32_t& r2,
                                        uint32_t& r3, uint32_t addr) {
    asm volatile("ldmatrix.sync.aligned.m8n8.x4.shared.b16 {%0,%1,%2,%3}, [%4];"
                 : "=r"(r0), "=r"(r1), "=r"(r2), "=r"(r3) : "r"(addr));
}
__device__ __forceinline__ void mma_16816(float* d, uint32_t a0, uint32_t a1,
                                          uint32_t a2, uint32_t a3,
                                          uint32_t b0, uint32_t b1) {
    asm volatile(
        "mma.sync.aligned.m16n8k16.row.col.f32.f16.f16.f32 "
        "{%0,%1,%2,%3}, {%4,%5,%6,%7}, {%8,%9}, {%0,%1,%2,%3};"
        : "+f"(d[0]), "+f"(d[1]), "+f"(d[2]), "+f"(d[3])
        : "r"(a0), "r"(a1), "r"(a2), "r"(a3), "r"(b0), "r"(b1));
}

// ---------------------------------------------------------------------------
// KG: head-shared Gram matrix, one block per (b,c) (64 blocks).
//   G[t,s] = sum_n C[t,n] B[s,n]; stored TRANSPOSED: g_Gt[b][c][s][t].
// ---------------------------------------------------------------------------
__global__ __launch_bounds__(256) void kG_bc(
    const float* __restrict__ Bm,     // [B,T,N]
    const float* __restrict__ Cm)     // [B,T,N]
{
    extern __shared__ float smem[];
    float* sB  = smem;                // [CHL][LDS_]
    float* sC  = sB + CHL * LDS_;
    float* sGT = sC + CHL * LDS_;     // [CHL][LDS_] G^T staging

    const int blk = blockIdx.x;       // b*NCH + c
    const int c = blk % NCH;
    const int b = blk / NCH;
    const int t0 = c * CHL;
    const int tid = threadIdx.x;

    for (int i = tid; i < CHL * NN / 4; i += 256) {
        const int r = i >> 4, q = i & 15;
        *(float4*)&sB[IDX(r, q * 4)] =
            __ldg((const float4*)(Bm + ((size_t)b * TLEN + t0 + r) * NN) + q);
        *(float4*)&sC[IDX(r, q * 4)] =
            __ldg((const float4*)(Cm + ((size_t)b * TLEN + t0 + r) * NN) + q);
    }
    __syncthreads();

    const int i = tid & 15;
    const int j = tid >> 4;

    float g[4][4];
    #pragma unroll
    for (int a0 = 0; a0 < 4; ++a0)
        #pragma unroll
        for (int a1 = 0; a1 < 4; ++a1) g[a0][a1] = 0.f;

    #pragma unroll 4
    for (int n4 = 0; n4 < NN / 4; ++n4) {
        float4 cv[4], bv[4];
        #pragma unroll
        for (int tj = 0; tj < 4; ++tj) cv[tj] = *(const float4*)&sC[IDX(j + 16 * tj, n4 * 4)];
        #pragma unroll
        for (int si = 0; si < 4; ++si) bv[si] = *(const float4*)&sB[IDX(i + 16 * si, n4 * 4)];
        #pragma unroll
        for (int tj = 0; tj < 4; ++tj)
            #pragma unroll
            for (int si = 0; si < 4; ++si) {
                g[tj][si] = fmaf(cv[tj].x, bv[si].x, g[tj][si]);
                g[tj][si] = fmaf(cv[tj].y, bv[si].y, g[tj][si]);
                g[tj][si] = fmaf(cv[tj].z, bv[si].z, g[tj][si]);
                g[tj][si] = fmaf(cv[tj].w, bv[si].w, g[tj][si]);
            }
    }

    #pragma unroll
    for (int si = 0; si < 4; ++si) {
        const int s = i + 16 * si;
        #pragma unroll
        for (int tj = 0; tj < 4; ++tj)
            sGT[IDX(s, j + 16 * tj)] = g[tj][si];
    }
    __syncthreads();

    float* Gp = g_Gt + (size_t)blk * (CHL * NN);
    for (int idx = tid; idx < CHL * NN / 4; idx += 256) {
        const int r = idx >> 4, q = idx & 15;
        *(float4*)(Gp + r * NN + 4 * q) = *(const float4*)&sGT[IDX(r, 4 * q)];
    }
}

// ---------------------------------------------------------------------------
// KA: fused intra-chunk kernel. One block per (b,h,c), 256 threads.
//   W^T   : sW[s,t] = (s<=t) ? exp(negA*(cum_t-cum_s))*delta_s*G^T[s,t] : 0
//   GEMM-S: S[p,n]  = sum_s r_s B[s,n] X[s,p]  -> g_S fp16; chunk 31 also -> hlast fp32
//   GEMM2 : y[t,p]  = sum_{s<=t} W[t,s] X[s,p]
// ---------------------------------------------------------------------------
__global__ __launch_bounds__(256) void kA_intra(
    const float* __restrict__ X,      // [B,T,H,P]
    const float* __restrict__ delta,  // [B,T,H]
    const float* __restrict__ Bm,     // [B,T,N]
    const float* __restrict__ A_log,  // [H]
    float* __restrict__ y,            // [B,T,H,P]
    float* __restrict__ hlast)        // [B,H,P,N]
{
    extern __shared__ float smem[];
    float* sB = smem;                 // [CHL][LDS_] raw B, later scaled by r_s
    float* sW = sB + CHL * LDS_;      // [CHL][LDS_] G^T, then W^T (in place)
    float* sX = sW + CHL * LDS_;      // [CHL][LDS_]

    __shared__ float sh_d[CHL], sh_cum[CHL], sh_r[CHL];
    __shared__ float sh_wsum[2];

    const int blk = blockIdx.x;            // (b*NH+h)*NCH + c
    const int c  = blk % NCH;
    const int hh = (blk / NCH) % NH;
    const int b  = blk / (NCH * NH);
    const int t0 = c * CHL;
    const int tid = threadIdx.x;
    const int lane = tid & 31;

    const float negA = -__expf(A_log[hh]);

    if (tid < CHL) {
        const float d = __ldg(delta + ((size_t)b * TLEN + t0 + tid) * NH + hh);
        sh_d[tid] = d;
        float v = d;
        #pragma unroll
        for (int off = 1; off < 32; off <<= 1) {
            const float t = __shfl_up_sync(0xffffffffu, v, off);
            if (lane >= off) v += t;
        }
        sh_cum[tid] = v;
        if (lane == 31) sh_wsum[tid >> 5] = v;
    }

    {
        const float* Gp = g_Gt + ((size_t)b * NCH + c) * (CHL * NN);
        for (int i = tid; i < CHL * NN / 4; i += 256) {
            const int r = i >> 4, q = i & 15;
            *(float4*)&sB[IDX(r, q * 4)] =
                __ldg((const float4*)(Bm + ((size_t)b * TLEN + t0 + r) * NN) + q);
            *(float4*)&sW[IDX(r, q * 4)] =
                __ldg((const float4*)(Gp + r * NN) + q);
            *(float4*)&sX[IDX(r, q * 4)] =
                __ldg((const float4*)(X + (((size_t)b * TLEN + t0 + r) * NH + hh) * PP) + q);
        }
    }
    __syncthreads();

    if (tid < CHL) {
        const float cum = sh_cum[tid] + (tid >= 32 ? sh_wsum[0] : 0.f);
        sh_cum[tid] = cum;
        const float cumTot = sh_wsum[0] + sh_wsum[1];
        g_a[(size_t)blk * CHL + tid] = __expf(negA * cum);
        sh_r[tid] = __expf(negA * (cumTot - cum)) * sh_d[tid];
        if (tid == 0) g_A[blk] = __expf(negA * cumTot);
    }
    __syncthreads();

    const int i = tid & 15;
    const int j = tid >> 4;

    // ---- W transform in place ----
    {
        const float ct0 = sh_cum[4 * i + 0];
        const float ct1 = sh_cum[4 * i + 1];
        const float ct2 = sh_cum[4 * i + 2];
        const float ct3 = sh_cum[4 * i + 3];
        #pragma unroll
        for (int sj = 0; sj < 4; ++sj) {
            const int s = 4 * j + sj;
            const float cs = sh_cum[s];
            const float ds = sh_d[s];
            float4 w = *(const float4*)&sW[IDX(s, 4 * i)];
            w.x = (s <= 4 * i + 0) ? __expf(fminf(negA * (ct0 - cs), 0.f)) * ds * w.x : 0.f;
            w.y = (s <= 4 * i + 1) ? __expf(fminf(negA * (ct1 - cs), 0.f)) * ds * w.y : 0.f;
            w.z = (s <= 4 * i + 2) ? __expf(fminf(negA * (ct2 - cs), 0.f)) * ds * w.z : 0.f;
            w.w = (s <= 4 * i + 3) ? __expf(fminf(negA * (ct3 - cs), 0.f)) * ds * w.w : 0.f;
            *(float4*)&sW[IDX(s, 4 * i)] = w;
        }
    }
    for (int idx = tid; idx < CHL * NN / 4; idx += 256) {
        const int r = idx >> 4, q = idx & 15;
        float4 v = *(float4*)&sB[IDX(r, q * 4)];
        const float rr = sh_r[r];
        v.x *= rr; v.y *= rr; v.z *= rr; v.w *= rr;
        *(float4*)&sB[IDX(r, q * 4)] = v;
    }
    __syncthreads();

    // ---- GEMM-S ----
    {
        float acc[4][4];
        #pragma unroll
        for (int a0 = 0; a0 < 4; ++a0)
            #pragma unroll
            for (int a1 = 0; a1 < 4; ++a1) acc[a0][a1] = 0.f;

        #pragma unroll 8
        for (int s = 0; s < CHL; ++s) {
            const float4 bv = *(const float4*)&sB[IDX(s, 4 * i)];
            const float4 xv = *(const float4*)&sX[IDX(s, 4 * j)];
            acc[0][0] = fmaf(xv.x, bv.x, acc[0][0]);
            acc[0][1] = fmaf(xv.x, bv.y, acc[0][1]);
            acc[0][2] = fmaf(xv.x, bv.z, acc[0][2]);
            acc[0][3] = fmaf(xv.x, bv.w, acc[0][3]);
            acc[1][0] = fmaf(xv.y, bv.x, acc[1][0]);
            acc[1][1] = fmaf(xv.y, bv.y, acc[1][1]);
            acc[1][2] = fmaf(xv.y, bv.z, acc[1][2]);
            acc[1][3] = fmaf(xv.y, bv.w, acc[1][3]);
            acc[2][0] = fmaf(xv.z, bv.x, acc[2][0]);
            acc[2][1] = fmaf(xv.z, bv.y, acc[2][1]);
            acc[2][2] = fmaf(xv.z, bv.z, acc[2][2]);
            acc[2][3] = fmaf(xv.z, bv.w, acc[2][3]);
            acc[3][0] = fmaf(xv.w, bv.x, acc[3][0]);
            acc[3][1] = fmaf(xv.w, bv.y, acc[3][1]);
            acc[3][2] = fmaf(xv.w, bv.z, acc[3][2]);
            acc[3][3] = fmaf(xv.w, bv.w, acc[3][3]);
        }
        __half2* Sp = g_S + (size_t)blk * (PP * NN / 2);
        #pragma unroll
        for (int pj = 0; pj < 4; ++pj) {
            const int p = 4 * j + pj;
            __half2 h01 = __floats2half2_rn(acc[pj][0], acc[pj][1]);
            __half2 h23 = __floats2half2_rn(acc[pj][2], acc[pj][3]);
            uint2 u;
            u.x = *(unsigned*)&h01;
            u.y = *(unsigned*)&h23;
            *(uint2*)(Sp + p * (NN / 2) + 2 * i) = u;
        }
        if (c == NCH - 1) {
            float* hp = hlast + ((size_t)(b * NH + hh)) * PP * NN;
            #pragma unroll
            for (int pj = 0; pj < 4; ++pj) {
                const int p = 4 * j + pj;
                *(float4*)(hp + p * NN + 4 * i) =
                    make_float4(acc[pj][0], acc[pj][1], acc[pj][2], acc[pj][3]);
            }
        }
    }

    // ---- GEMM2 (triangular) ----
    {
        const int sBound = ((tid >> 5) + 1) * 8;
        float acc[4][4];
        #pragma unroll
        for (int a0 = 0; a0 < 4; ++a0)
            #pragma unroll
            for (int a1 = 0; a1 < 4; ++a1) acc[a0][a1] = 0.f;

        #pragma unroll 8
        for (int s = 0; s < sBound; ++s) {
            const float4 wv = *(const float4*)&sW[IDX(s, 4 * j)];
            const float4 xv = *(const float4*)&sX[IDX(s, 4 * i)];
            acc[0][0] = fmaf(wv.x, xv.x, acc[0][0]);
            acc[0][1] = fmaf(wv.x, xv.y, acc[0][1]);
            acc[0][2] = fmaf(wv.x, xv.z, acc[0][2]);
            acc[0][3] = fmaf(wv.x, xv.w, acc[0][3]);
            acc[1][0] = fmaf(wv.y, xv.x, acc[1][0]);
            acc[1][1] = fmaf(wv.y, xv.y, acc[1][1]);
            acc[1][2] = fmaf(wv.y, xv.z, acc[1][2]);
            acc[1][3] = fmaf(wv.y, xv.w, acc[1][3]);
            acc[2][0] = fmaf(wv.z, xv.x, acc[2][0]);
            acc[2][1] = fmaf(wv.z, xv.y, acc[2][1]);
            acc[2][2] = fmaf(wv.z, xv.z, acc[2][2]);
            acc[2][3] = fmaf(wv.z, xv.w, acc[2][3]);
            acc[3][0] = fmaf(wv.w, xv.x, acc[3][0]);
            acc[3][1] = fmaf(wv.w, xv.y, acc[3][1]);
            acc[3][2] = fmaf(wv.w, xv.z, acc[3][2]);
            acc[3][3] = fmaf(wv.w, xv.w, acc[3][3]);
        }
        #pragma unroll
        for (int tj = 0; tj < 4; ++tj) {
            const int t = 4 * j + tj;
            float* yrow = y + (((size_t)b * TLEN + t0 + t) * NH + hh) * PP;
            *(float4*)(yrow + 4 * i) =
                make_float4(acc[tj][0], acc[tj][1], acc[tj][2], acc[tj][3]);
        }
    }
}

// ---------------------------------------------------------------------------
// K2: cross-chunk scan, one thread per (bh, p, n-pair). hlast RMW adds A31*H0[31].
// ---------------------------------------------------------------------------
__global__ __launch_bounds__(256) void k2_scan(float* __restrict__ hlast) // [B,H,P,N]
{
    const int idx = blockIdx.x * 256 + threadIdx.x;
    const int bh  = idx >> 11;
    const int pn2 = idx & 2047;

    float2 h = make_float2(0.f, 0.f);
    #pragma unroll
    for (int c = 0; c < NCH; ++c) {
        const size_t off = ((size_t)bh * NCH + c) * (PP * NN / 2) + pn2;
        g_H0[off] = __floats2half2_rn(h.x, h.y);
        if (c < NCH - 1) {
            const float A = g_A[bh * NCH + c];
            const float2 s = __half22float2(g_S[off]);
            h.x = fmaf(A, h.x, s.x);
            h.y = fmaf(A, h.y, s.y);
        }
    }
    const float A31 = g_A[bh * NCH + (NCH - 1)];
    float2* hp = (float2*)hlast + (size_t)bh * (PP * NN / 2) + pn2;
    float2 v = *hp;
    v.x = fmaf(A31, h.x, v.x);
    v.y = fmaf(A31, h.y, v.y);
    *hp = v;
}

// ---------------------------------------------------------------------------
// KC: inter-chunk correction via tensor cores. One block per (b,h,c).
//   y[t,p] += sum_n (a_t*C[t,n]) * H0[p,n]   -- a_t folded into fp16 C tile.
// D[p,t] = A(H0[p,k]) x B(Ca[t,k]); mma.m16n8k16.row.col; ldmatrix no-trans.
// ---------------------------------------------------------------------------
__global__ __launch_bounds__(256) void kC_corr(
    const float* __restrict__ Cm,
    float* __restrict__ y)
{
    __shared__ __align__(16) __half sCa[CHL * HSTR];  // a_t * C[t][k], 144B rows
    __shared__ __align__(16) __half sH [PP  * HSTR];  // H0[p][k]

    const int blk = blockIdx.x;
    const int c  = blk % NCH;
    const int hh = (blk / NCH) % NH;
    const int b  = blk / (NCH * NH);
    const int t0 = c * CHL;
    const int tid = threadIdx.x;
    const int lane = tid & 31;
    const int w = tid >> 5;

    // ---- stage Ca = a_t * C (fp32 mul, then fp16) ----
    for (int i = tid; i < CHL * NN / 4; i += 256) {
        const int r = i >> 4, q = i & 15;
        const float a = __ldg(g_a + (size_t)blk * CHL + r);
        const float4 v = __ldg((const float4*)(Cm + ((size_t)b * TLEN + t0 + r) * NN) + q);
        __half2 h01 = __floats2half2_rn(a * v.x, a * v.y);
        __half2 h23 = __floats2half2_rn(a * v.z, a * v.w);
        uint2 u;
        u.x = *(unsigned*)&h01;
        u.y = *(unsigned*)&h23;
        *(uint2*)&sCa[r * HSTR + 4 * q] = u;
    }
    // ---- stage H0 (already fp16) ----
    {
        const __half2* Hp = g_H0 + (size_t)blk * (PP * NN / 2);
        for (int i = tid; i < PP * NN / 4; i += 256) {
            const int r = i >> 4, q = i & 15;
            const uint2 u = __ldg((const uint2*)(Hp + r * (NN / 2)) + q);
            *(uint2*)&sH[r * HSTR + 4 * q] = u;
        }
    }
    __syncthreads();

    // warp tile: p rows [p0, p0+16), t cols [t0q, t0q+32)
    const int p0  = (w & 3) * 16;
    const int t0q = (w >> 2) * 32;

    float acc[4][4];
    #pragma unroll
    for (int a0 = 0; a0 < 4; ++a0)
        #pragma unroll
        for (int a1 = 0; a1 < 4; ++a1) acc[a0][a1] = 0.f;

    #pragma unroll
    for (int ks = 0; ks < 4; ++ks) {          // k = ks*16
        uint32_t a0, a1, a2, a3;
        ldsm_x4(a0, a1, a2, a3,
                sm_u32(&sH[(p0 + (lane & 15)) * HSTR + ks * 16 + ((lane >> 4) << 3)]));
        #pragma unroll
        for (int ntp = 0; ntp < 2; ++ntp) {   // two n8-tile pairs
            uint32_t b0, b1, b2, b3;
            const int trow = t0q + ntp * 16 + ((lane >> 4) << 3) + (lane & 7);
            const int kcol = ks * 16 + (((lane >> 3) & 1) << 3);
            ldsm_x4(b0, b1, b2, b3, sm_u32(&sCa[trow * HSTR + kcol]));
            mma_16816(acc[ntp * 2],     a0, a1, a2, a3, b0, b1);
            mma_16816(acc[ntp * 2 + 1], a0, a1, a2, a3, b2, b3);
        }
    }

    // ---- epilogue: direct RMW of y (a_t already applied) ----
    // D[p][t]: c0=D[g][2c], c1=D[g][2c+1], c2=D[g+8][2c], c3=D[g+8][2c+1]
    const int g_row = lane >> 2;        // p offset
    const int tc    = (lane & 3) * 2;   // t offset
    #pragma unroll
    for (int nt = 0; nt < 4; ++nt) {
        const int t_a = t0 + t0q + nt * 8 + tc;
        const int p_a = p0 + g_row;
        float* r0 = y + (((size_t)b * TLEN + t_a) * NH + hh) * PP;
        float* r1 = r0 + NH * PP;       // t_a + 1
        r0[p_a]     += acc[nt][0];
        r1[p_a]     += acc[nt][1];
        r0[p_a + 8] += acc[nt][2];
        r1[p_a + 8] += acc[nt][3];
    }
}

extern "C" void kernel_launch(void* const* d_in, const int* in_sizes, int n_in,
                              void* d_out, int out_size) {
    const float* X     = (const float*)d_in[0];
    const float* delta = (const float*)d_in[1];
    const float* Bm    = (const float*)d_in[2];
    const float* Cm    = (const float*)d_in[3];
    const float* A_log = (const float*)d_in[4];

    float* y     = (float*)d_out;
    float* hlast = y + (size_t)BSZ * TLEN * NH * PP;

    const int big_smem = 3 * CHL * LDS_ * (int)sizeof(float);  // 52224 B
    cudaFuncSetAttribute(kG_bc,    cudaFuncAttributeMaxDynamicSharedMemorySize, big_smem);
    cudaFuncSetAttribute(kA_intra, cudaFuncAttributeMaxDynamicSharedMemorySize, big_smem);

    kG_bc<<<BSZ * NCH, 256, big_smem>>>(Bm, Cm);                                 // 64 blocks
    kA_intra<<<BSZ * NH * NCH, 256, big_smem>>>(X, delta, Bm, A_log, y, hlast);  // 1024 blocks
    k2_scan<<<(BSZ * NH * PP * NN / 2) / 256, 256>>>(hlast);                     // 256 blocks
    kC_corr<<<BSZ * NH * NCH, 256>>>(Cm, y);                                     // 1024 blocks
}